// round 7
// baseline (speedup 1.0000x reference)
#include <cuda_runtime.h>
#include <cuda_fp16.h>
#include <cstdint>

#define NN   100000
#define EE   1600000
#define F_IN 128
#define HID  64
#define OUTD 40
#define NBIN 64

// Scratch (device globals — allocation is forbidden)
__device__ __half g_uA[NN * HID];
__device__ __half g_uB[NN * HID];
__device__ int    g_deg[NN];
__device__ float  g_dis[NN];
__device__ __half g_dish[NN];
__device__ int    g_rowptr[NN];
__device__ int    g_cursor[NN];
__device__ int    g_colidx[EE];
__device__ int    g_bsum[128];
__device__ int    g_perm[NN];
__device__ int    g_bins[NBIN];
__device__ int    g_bincur[NBIN];

// ---------------------------------------------------------------------------
// scan1: per-1024-chunk exclusive scan of deg -> rowptr + dis/dish tables
// ---------------------------------------------------------------------------
__global__ void scan1_kernel(const int* __restrict__ deg, int* __restrict__ rowptr,
                             float* __restrict__ dis, __half* __restrict__ dish,
                             int* __restrict__ bsum, int n) {
    __shared__ int sh[256];
    int t = threadIdx.x;
    int base = blockIdx.x * 1024 + t * 4;
    int v[4]; int s = 0;
    #pragma unroll
    for (int j = 0; j < 4; j++) {
        v[j] = (base + j < n) ? deg[base + j] : 0;
        if (base + j < n) {
            float r = rsqrtf((float)(v[j] + 1));
            dis[base + j] = r;
            dish[base + j] = __float2half_rn(r);
        }
        s += v[j];
    }
    sh[t] = s;
    for (int off = 1; off < 256; off <<= 1) {
        __syncthreads();
        int x = (t >= off) ? sh[t - off] : 0;
        __syncthreads();
        sh[t] += x;
    }
    __syncthreads();
    int excl = sh[t] - s;
    int run = 0;
    #pragma unroll
    for (int j = 0; j < 4; j++) {
        if (base + j < n) rowptr[base + j] = excl + run;
        run += v[j];
    }
    if (t == 255) bsum[blockIdx.x] = sh[255];
}

__global__ void scan2_kernel(int* __restrict__ bsum, int nb) {
    __shared__ int sh[128];
    int t = threadIdx.x;
    int v = (t < nb) ? bsum[t] : 0;
    sh[t] = v;
    for (int off = 1; off < 128; off <<= 1) {
        __syncthreads();
        int x = (t >= off) ? sh[t - off] : 0;
        __syncthreads();
        sh[t] += x;
    }
    __syncthreads();
    if (t < nb) bsum[t] = sh[t] - v;
}

// scan3 + per-block degree histogram (64 bins) merged to global
__global__ void scan3_kernel(const int* __restrict__ bsum, int* __restrict__ rowptr,
                             int* __restrict__ cursor, const int* __restrict__ deg,
                             int* __restrict__ bins, int n) {
    __shared__ int sh[NBIN];
    int t = threadIdx.x;
    if (t < NBIN) sh[t] = 0;
    __syncthreads();
    int i = blockIdx.x * blockDim.x + t;
    if (i < n) {
        int r = rowptr[i] + bsum[i >> 10];
        rowptr[i] = r;
        cursor[i] = r;
        int b = min(deg[i], NBIN - 1);
        atomicAdd(&sh[b], 1);
    }
    __syncthreads();
    if (t < NBIN && sh[t]) atomicAdd(&bins[t], sh[t]);
}

// exclusive scan of 64 bins -> bincur
__global__ void binscan_kernel(const int* __restrict__ bins, int* __restrict__ bincur) {
    if (threadIdx.x == 0) {
        int s = 0;
        #pragma unroll
        for (int i = 0; i < NBIN; i++) { int x = bins[i]; bincur[i] = s; s += x; }
    }
}

// ---------------------------------------------------------------------------
// Heterogeneous: [0,premulB): premul uA by dish;
//                [premulB, premulB+scatB): edge scatter;
//                rest: perm scatter by degree bin.
// ---------------------------------------------------------------------------
__global__ void prep_mega_kernel(const int* __restrict__ src, const int* __restrict__ dst,
                                 int* __restrict__ cursor, int* __restrict__ colidx,
                                 const int* __restrict__ deg, int* __restrict__ bincur,
                                 int* __restrict__ perm,
                                 const __half* __restrict__ dish, __half* __restrict__ u,
                                 int n, int E, int premulB, int scatB) {
    int b = blockIdx.x;
    int t = threadIdx.x;
    if (b < premulB) {
        int idx = b * 256 + t;              // node-lane index: v*8 + h
        int v = idx >> 3;
        if (v < n) {
            uint4* uv = (uint4*)u;
            uint4 x = uv[idx];
            __half2 w = __half2half2(__ldg(dish + v));
            *(__half2*)&x.x = __hmul2(w, *(__half2*)&x.x);
            *(__half2*)&x.y = __hmul2(w, *(__half2*)&x.y);
            *(__half2*)&x.z = __hmul2(w, *(__half2*)&x.z);
            *(__half2*)&x.w = __hmul2(w, *(__half2*)&x.w);
            uv[idx] = x;
        }
    } else if (b < premulB + scatB) {
        int e = (b - premulB) * 256 + t;
        if (e < E) {
            int p = atomicAdd(&cursor[dst[e]], 1);
            colidx[p] = src[e];
        }
    } else {
        int v = (b - premulB - scatB) * 256 + t;
        if (v < n) {
            int bin = min(__ldg(deg + v), NBIN - 1);
            int pos = atomicAdd(&bincur[bin], 1);
            perm[pos] = v;
        }
    }
}

// ---------------------------------------------------------------------------
// Layer-0 GEMM: X fp32 [n,128] @ W [128,64] + b -> u fp16 (unscaled).
// Heterogeneous grid: trailing blocks do the degree histogram.
// ---------------------------------------------------------------------------
__global__ void gemm0_kernel(const float* __restrict__ X,
                             const float* __restrict__ W,
                             const float* __restrict__ B,
                             __half* __restrict__ u, int n,
                             const int* __restrict__ edge_dst, int E,
                             int* __restrict__ deg, int gemmBlocks) {
    constexpr int K = F_IN;
    constexpr int KC = 64;
    constexpr int XSTR = KC + 1;
    __shared__ float  Ws[KC * 64];
    __shared__ float2 Xd[32 * XSTR];

    int t = threadIdx.x;

    if ((int)blockIdx.x >= gemmBlocks) {
        int nb = gridDim.x - gemmBlocks;
        int stride = nb * 256;
        for (int e = (blockIdx.x - gemmBlocks) * 256 + t; e < E; e += stride)
            atomicAdd(&deg[__ldg(edge_dst + e)], 1);
        return;
    }

    int row0 = blockIdx.x * 32;
    int tix = t & 15;
    int tiy = t >> 4;

    unsigned long long acc[2][2];
    acc[0][0] = acc[0][1] = acc[1][0] = acc[1][1] = 0ull;

    for (int k0 = 0; k0 < K; k0 += KC) {
        #pragma unroll
        for (int i = t; i < KC * 64 / 4; i += 256)
            ((float4*)Ws)[i] = ((const float4*)(W + k0 * 64))[i];
        #pragma unroll
        for (int i = t; i < 32 * KC / 4; i += 256) {
            int r = i / (KC / 4);
            int c = (i % (KC / 4)) * 4;
            int gr = row0 + r;
            float4 x = {0.f, 0.f, 0.f, 0.f};
            if (gr < n) x = *(const float4*)(X + (size_t)gr * K + k0 + c);
            float2* p = &Xd[r * XSTR + c];
            p[0] = make_float2(x.x, x.x); p[1] = make_float2(x.y, x.y);
            p[2] = make_float2(x.z, x.z); p[3] = make_float2(x.w, x.w);
        }
        __syncthreads();

        #pragma unroll
        for (int k = 0; k < KC; k++) {
            ulonglong2 w = *reinterpret_cast<const ulonglong2*>(&Ws[k * 64 + tix * 4]);
            unsigned long long x0 = *reinterpret_cast<const unsigned long long*>(&Xd[(tiy * 2 + 0) * XSTR + k]);
            unsigned long long x1 = *reinterpret_cast<const unsigned long long*>(&Xd[(tiy * 2 + 1) * XSTR + k]);
            asm("fma.rn.f32x2 %0, %1, %2, %0;" : "+l"(acc[0][0]) : "l"(x0), "l"(w.x));
            asm("fma.rn.f32x2 %0, %1, %2, %0;" : "+l"(acc[0][1]) : "l"(x0), "l"(w.y));
            asm("fma.rn.f32x2 %0, %1, %2, %0;" : "+l"(acc[1][0]) : "l"(x1), "l"(w.x));
            asm("fma.rn.f32x2 %0, %1, %2, %0;" : "+l"(acc[1][1]) : "l"(x1), "l"(w.y));
        }
        __syncthreads();
    }

    float4 b4 = *(const float4*)(B + tix * 4);
    #pragma unroll
    for (int r = 0; r < 2; r++) {
        int gr = row0 + tiy * 2 + r;
        if (gr >= n) continue;
        float o0 = __uint_as_float((unsigned)(acc[r][0] & 0xffffffffu)) + b4.x;
        float o1 = __uint_as_float((unsigned)(acc[r][0] >> 32))         + b4.y;
        float o2 = __uint_as_float((unsigned)(acc[r][1] & 0xffffffffu)) + b4.z;
        float o3 = __uint_as_float((unsigned)(acc[r][1] >> 32))         + b4.w;
        __half2 h01 = __floats2half2_rn(o0, o1);
        __half2 h23 = __floats2half2_rn(o2, o3);
        uint2 pk = make_uint2(*(unsigned*)&h01, *(unsigned*)&h23);
        *(uint2*)(u + (size_t)gr * 64 + tix * 4) = pk;
    }
}

// ---------------------------------------------------------------------------
// Unweighted aggregate of node v (8 lanes, lane h): out = relu(sum+self)*dis[v]
// ---------------------------------------------------------------------------
__device__ __forceinline__ void aggregate_node(
    int v, int h,
    const int* __restrict__ rowptr, const int* __restrict__ deg,
    const int* __restrict__ colidx, const float* __restrict__ dis,
    const __half* __restrict__ u,
    float out[8])
{
    const uint4* uv = (const uint4*)u;
    const __half2 z = __float2half2_rn(0.f);
    __half2 s0[4] = {z, z, z, z};
    __half2 s1[4] = {z, z, z, z};

    int p0 = __ldg(rowptr + v);
    int d  = __ldg(deg + v);

    int j = 0;
    for (; j + 2 <= d; j += 2) {
        int c0 = __ldg(colidx + p0 + j);
        int c1 = __ldg(colidx + p0 + j + 1);
        uint4 x0 = __ldg(uv + (size_t)c0 * 8 + h);
        uint4 x1 = __ldg(uv + (size_t)c1 * 8 + h);
        s0[0] = __hadd2(s0[0], *(__half2*)&x0.x);
        s0[1] = __hadd2(s0[1], *(__half2*)&x0.y);
        s0[2] = __hadd2(s0[2], *(__half2*)&x0.z);
        s0[3] = __hadd2(s0[3], *(__half2*)&x0.w);
        s1[0] = __hadd2(s1[0], *(__half2*)&x1.x);
        s1[1] = __hadd2(s1[1], *(__half2*)&x1.y);
        s1[2] = __hadd2(s1[2], *(__half2*)&x1.z);
        s1[3] = __hadd2(s1[3], *(__half2*)&x1.w);
    }
    if (j < d) {
        int c0 = __ldg(colidx + p0 + j);
        uint4 x0 = __ldg(uv + (size_t)c0 * 8 + h);
        s0[0] = __hadd2(s0[0], *(__half2*)&x0.x);
        s0[1] = __hadd2(s0[1], *(__half2*)&x0.y);
        s0[2] = __hadd2(s0[2], *(__half2*)&x0.z);
        s0[3] = __hadd2(s0[3], *(__half2*)&x0.w);
    }

    uint4 ps = __ldg(uv + (size_t)v * 8 + h);
    float dv = __ldg(dis + v);

    #pragma unroll
    for (int k = 0; k < 4; k++) {
        float2 f0 = __half22float2(s0[k]);
        float2 f1 = __half22float2(s1[k]);
        float2 fs = __half22float2(*((__half2*)&ps.x + k));
        out[k * 2 + 0] = fmaxf(f0.x + f1.x + fs.x, 0.f) * dv;
        out[k * 2 + 1] = fmaxf(f0.y + f1.y + fs.y, 0.f) * dv;
    }
}

// ---------------------------------------------------------------------------
// Fused pull + GEMM64 over degree-sorted perm.
// ---------------------------------------------------------------------------
__global__ void fused64_kernel(const int* __restrict__ perm,
                               const int* __restrict__ rowptr,
                               const int* __restrict__ deg,
                               const int* __restrict__ colidx,
                               const float* __restrict__ dis,
                               const __half* __restrict__ u_in,
                               const float* __restrict__ W,
                               const float* __restrict__ B,
                               __half* __restrict__ u_out, int n) {
    constexpr int KC = 64;
    constexpr int XSTR = KC + 1;
    __shared__ float  Ws[KC * 64];
    __shared__ float2 Xd[32 * XSTR];

    int t = threadIdx.x;
    int row0 = blockIdx.x * 32;

    #pragma unroll
    for (int i = t; i < KC * 64 / 4; i += 256)
        ((float4*)Ws)[i] = ((const float4*)W)[i];

    // Phase 1: aggregate 32 permuted nodes -> Xd
    {
        int r = t >> 3;
        int h = t & 7;
        int idx = row0 + r;
        float xv[8] = {0,0,0,0,0,0,0,0};
        if (idx < n) {
            int v = __ldg(perm + idx);
            aggregate_node(v, h, rowptr, deg, colidx, dis, u_in, xv);
        }
        float2* p = &Xd[r * XSTR + h * 8];
        #pragma unroll
        for (int k = 0; k < 8; k++) p[k] = make_float2(xv[k], xv[k]);
    }
    __syncthreads();

    // Phase 2: 32x64 GEMM
    int tix = t & 15;
    int tiy = t >> 4;
    unsigned long long acc[2][2];
    acc[0][0] = acc[0][1] = acc[1][0] = acc[1][1] = 0ull;

    #pragma unroll
    for (int k = 0; k < KC; k++) {
        ulonglong2 w = *reinterpret_cast<const ulonglong2*>(&Ws[k * 64 + tix * 4]);
        unsigned long long x0 = *reinterpret_cast<const unsigned long long*>(&Xd[(tiy * 2 + 0) * XSTR + k]);
        unsigned long long x1 = *reinterpret_cast<const unsigned long long*>(&Xd[(tiy * 2 + 1) * XSTR + k]);
        asm("fma.rn.f32x2 %0, %1, %2, %0;" : "+l"(acc[0][0]) : "l"(x0), "l"(w.x));
        asm("fma.rn.f32x2 %0, %1, %2, %0;" : "+l"(acc[0][1]) : "l"(x0), "l"(w.y));
        asm("fma.rn.f32x2 %0, %1, %2, %0;" : "+l"(acc[1][0]) : "l"(x1), "l"(w.x));
        asm("fma.rn.f32x2 %0, %1, %2, %0;" : "+l"(acc[1][1]) : "l"(x1), "l"(w.y));
    }

    float4 b4 = *(const float4*)(B + tix * 4);
    #pragma unroll
    for (int r = 0; r < 2; r++) {
        int idx = row0 + tiy * 2 + r;
        if (idx >= n) continue;
        int v = __ldg(perm + idx);
        float s = __ldg(dis + v);
        float o0 = (__uint_as_float((unsigned)(acc[r][0] & 0xffffffffu)) + b4.x) * s;
        float o1 = (__uint_as_float((unsigned)(acc[r][0] >> 32))         + b4.y) * s;
        float o2 = (__uint_as_float((unsigned)(acc[r][1] & 0xffffffffu)) + b4.z) * s;
        float o3 = (__uint_as_float((unsigned)(acc[r][1] >> 32))         + b4.w) * s;
        __half2 h01 = __floats2half2_rn(o0, o1);
        __half2 h23 = __floats2half2_rn(o2, o3);
        uint2 pk = make_uint2(*(unsigned*)&h01, *(unsigned*)&h23);
        *(uint2*)(u_out + (size_t)v * 64 + tix * 4) = pk;
    }
}

// ---------------------------------------------------------------------------
// Fused pull + head GEMM (K=64, NOUT=40), fp32 output, perm order.
// ---------------------------------------------------------------------------
__global__ void fused_head_kernel(const int* __restrict__ perm,
                                  const int* __restrict__ rowptr,
                                  const int* __restrict__ deg,
                                  const int* __restrict__ colidx,
                                  const float* __restrict__ dis,
                                  const __half* __restrict__ u_in,
                                  const float* __restrict__ W,
                                  const float* __restrict__ B,
                                  float* __restrict__ out, int n) {
    constexpr int K = HID, NOUT = OUTD;
    __shared__ float Ws[K * NOUT];
    __shared__ float Xs[32 * K];

    int t = threadIdx.x;
    int row0 = blockIdx.x * 32;

    #pragma unroll 4
    for (int i = t; i < K * NOUT; i += 256) Ws[i] = W[i];

    {
        int r = t >> 3;
        int h = t & 7;
        int idx = row0 + r;
        float xv[8] = {0,0,0,0,0,0,0,0};
        if (idx < n) {
            int v = __ldg(perm + idx);
            aggregate_node(v, h, rowptr, deg, colidx, dis, u_in, xv);
        }
        float* p = &Xs[r * K + h * 8];
        #pragma unroll
        for (int k = 0; k < 8; k++) p[k] = xv[k];
    }
    __syncthreads();

    int warp = t >> 5, lane = t & 31;
    int r0 = warp * 4;
    float acc0[4] = {0.f, 0.f, 0.f, 0.f};
    float acc1[4] = {0.f, 0.f, 0.f, 0.f};

    #pragma unroll
    for (int k = 0; k < K; k++) {
        float w0 = Ws[k * NOUT + lane];
        float w1 = (lane + 32 < NOUT) ? Ws[k * NOUT + lane + 32] : 0.f;
        #pragma unroll
        for (int r = 0; r < 4; r++) {
            float xv = Xs[(r0 + r) * K + k];
            acc0[r] = fmaf(xv, w0, acc0[r]);
            acc1[r] = fmaf(xv, w1, acc1[r]);
        }
    }

    float b0 = B[lane];
    float b1 = (lane + 32 < NOUT) ? B[lane + 32] : 0.f;
    #pragma unroll
    for (int r = 0; r < 4; r++) {
        int idx = row0 + r0 + r;
        if (idx >= n) continue;
        int v = __ldg(perm + idx);
        out[(size_t)v * NOUT + lane] = acc0[r] + b0;
        if (lane + 32 < NOUT) out[(size_t)v * NOUT + lane + 32] = acc1[r] + b1;
    }
}

// ---------------------------------------------------------------------------
extern "C" void kernel_launch(void* const* d_in, const int* in_sizes, int n_in,
                              void* d_out, int out_size) {
    const float* x    = (const float*)d_in[0];
    const int*   ei   = (const int*)d_in[1];
    const float* W0   = (const float*)d_in[2];
    const float* b0   = (const float*)d_in[3];
    const float* W1   = (const float*)d_in[4];
    const float* b1   = (const float*)d_in[5];
    const float* W2   = (const float*)d_in[6];
    const float* b2   = (const float*)d_in[7];
    const float* Wout = (const float*)d_in[8];
    const float* bout = (const float*)d_in[9];
    float* out = (float*)d_out;

    const int N = in_sizes[0] / F_IN;
    const int E = in_sizes[1] / 2;
    const int* src = ei;
    const int* dst = ei + E;

    __half *uA, *uB, *dish;
    float *dis;
    int *deg, *rowptr, *cursor, *colidx, *bsum, *perm, *bins, *bincur;
    cudaGetSymbolAddress((void**)&uA,     g_uA);
    cudaGetSymbolAddress((void**)&uB,     g_uB);
    cudaGetSymbolAddress((void**)&deg,    g_deg);
    cudaGetSymbolAddress((void**)&dis,    g_dis);
    cudaGetSymbolAddress((void**)&dish,   g_dish);
    cudaGetSymbolAddress((void**)&rowptr, g_rowptr);
    cudaGetSymbolAddress((void**)&cursor, g_cursor);
    cudaGetSymbolAddress((void**)&colidx, g_colidx);
    cudaGetSymbolAddress((void**)&bsum,   g_bsum);
    cudaGetSymbolAddress((void**)&perm,   g_perm);
    cudaGetSymbolAddress((void**)&bins,   g_bins);
    cudaGetSymbolAddress((void**)&bincur, g_bincur);

    const int TPB = 256;
    int gemmBlocks = (N + 31) / 32;
    int countBlocks = 2048;
    dim3 fused0_grid(gemmBlocks + countBlocks);
    dim3 layer_grid(gemmBlocks);
    int nscan = (N + 1023) / 1024;
    int nodeBlocks = (N + TPB - 1) / TPB;

    int premulB = (N * 8 + TPB - 1) / TPB;
    int scatB   = (E + TPB - 1) / TPB;
    dim3 mega_grid(premulB + scatB + nodeBlocks);

    // Layer-0 GEMM (no dis dependency) fused with degree count
    cudaMemsetAsync(deg, 0, N * sizeof(int), 0);
    cudaMemsetAsync(bins, 0, NBIN * sizeof(int), 0);
    gemm0_kernel<<<fused0_grid, TPB>>>(x, W0, b0, uA, N, dst, E, deg, gemmBlocks);

    // CSR build + dis tables + degree histogram
    scan1_kernel<<<nscan, 256>>>(deg, rowptr, dis, dish, bsum, N);
    scan2_kernel<<<1, 128>>>(bsum, nscan);
    scan3_kernel<<<nodeBlocks, TPB>>>(bsum, rowptr, cursor, deg, bins, N);
    binscan_kernel<<<1, 32>>>(bins, bincur);
    // premul uA by dish | edge scatter | perm scatter
    prep_mega_kernel<<<mega_grid, TPB>>>(src, dst, cursor, colidx, deg, bincur,
                                         perm, dish, uA, N, E, premulB, scatB);

    // Layer 1..2 fused pull+GEMM, head
    fused64_kernel<<<layer_grid, TPB>>>(perm, rowptr, deg, colidx, dis, uA, W1, b1, uB, N);
    fused64_kernel<<<layer_grid, TPB>>>(perm, rowptr, deg, colidx, dis, uB, W2, b2, uA, N);
    fused_head_kernel<<<layer_grid, TPB>>>(perm, rowptr, deg, colidx, dis, uA, Wout, bout, out, N);
}

// round 8
// speedup vs baseline: 1.0167x; 1.0167x over previous
#include <cuda_runtime.h>
#include <cuda_fp16.h>
#include <cstdint>

#define NN   100000
#define EE   1600000
#define F_IN 128
#define HID  64
#define OUTD 40

// Scratch (device globals — allocation is forbidden)
__device__ __half g_uA[NN * HID];
__device__ __half g_uB[NN * HID];
__device__ int    g_deg[NN];
__device__ float  g_dis[NN];
__device__ __half g_dish[NN];
__device__ int    g_rowptr[NN];
__device__ int    g_cursor[NN];
__device__ int    g_colidx[EE];
__device__ int    g_bsum[128];

// ---------------------------------------------------------------------------
// scan1: per-1024-chunk exclusive scan of deg -> rowptr + dis/dish tables
// ---------------------------------------------------------------------------
__global__ void scan1_kernel(const int* __restrict__ deg, int* __restrict__ rowptr,
                             float* __restrict__ dis, __half* __restrict__ dish,
                             int* __restrict__ bsum, int n) {
    __shared__ int sh[256];
    int t = threadIdx.x;
    int base = blockIdx.x * 1024 + t * 4;
    int v[4]; int s = 0;
    #pragma unroll
    for (int j = 0; j < 4; j++) {
        v[j] = (base + j < n) ? deg[base + j] : 0;
        if (base + j < n) {
            float r = rsqrtf((float)(v[j] + 1));
            dis[base + j] = r;
            dish[base + j] = __float2half_rn(r);
        }
        s += v[j];
    }
    sh[t] = s;
    for (int off = 1; off < 256; off <<= 1) {
        __syncthreads();
        int x = (t >= off) ? sh[t - off] : 0;
        __syncthreads();
        sh[t] += x;
    }
    __syncthreads();
    int excl = sh[t] - s;
    int run = 0;
    #pragma unroll
    for (int j = 0; j < 4; j++) {
        if (base + j < n) rowptr[base + j] = excl + run;
        run += v[j];
    }
    if (t == 255) bsum[blockIdx.x] = sh[255];
}

// ---------------------------------------------------------------------------
// scan3: finalize rowptr/cursor; each block computes the bsum prefix itself
// (nb <= 128 entries), absorbing the old scan2 kernel.
// ---------------------------------------------------------------------------
__global__ void scan3_kernel(const int* __restrict__ bsum, int* __restrict__ rowptr,
                             int* __restrict__ cursor, int n, int nb) {
    __shared__ int sh[128];
    int t = threadIdx.x;
    if (t < 128) sh[t] = (t < nb) ? bsum[t] : 0;
    __syncthreads();
    for (int off = 1; off < 128; off <<= 1) {
        int x = (t < 128 && t >= off) ? sh[t - off] : 0;
        __syncthreads();
        if (t < 128) sh[t] += x;
        __syncthreads();
    }
    int i = blockIdx.x * blockDim.x + t;
    if (i < n) {
        int c = i >> 10;
        int excl = (c == 0) ? 0 : sh[c - 1];
        int r = rowptr[i] + excl;
        rowptr[i] = r;
        cursor[i] = r;
    }
}

__global__ void scatter_kernel(const int* __restrict__ src, const int* __restrict__ dst,
                               int* __restrict__ cursor, int* __restrict__ colidx, int E) {
    int e = blockIdx.x * blockDim.x + threadIdx.x;
    if (e < E) {
        int p = atomicAdd(&cursor[dst[e]], 1);
        colidx[p] = src[e];
    }
}

// ---------------------------------------------------------------------------
// Layer-0 GEMM: X fp32 [n,128] @ W [128,64] + b -> u fp16 (unscaled).
// Heterogeneous grid: trailing blocks do the degree histogram.
// ---------------------------------------------------------------------------
__global__ void gemm0_kernel(const float* __restrict__ X,
                             const float* __restrict__ W,
                             const float* __restrict__ B,
                             __half* __restrict__ u, int n,
                             const int* __restrict__ edge_dst, int E,
                             int* __restrict__ deg, int gemmBlocks) {
    constexpr int K = F_IN;
    constexpr int KC = 64;
    constexpr int XSTR = KC + 1;
    __shared__ float  Ws[KC * 64];
    __shared__ float2 Xd[32 * XSTR];

    int t = threadIdx.x;

    if ((int)blockIdx.x >= gemmBlocks) {
        int nb = gridDim.x - gemmBlocks;
        int stride = nb * 256;
        for (int e = (blockIdx.x - gemmBlocks) * 256 + t; e < E; e += stride)
            atomicAdd(&deg[__ldg(edge_dst + e)], 1);
        return;
    }

    int row0 = blockIdx.x * 32;
    int tix = t & 15;
    int tiy = t >> 4;

    unsigned long long acc[2][2];
    acc[0][0] = acc[0][1] = acc[1][0] = acc[1][1] = 0ull;

    for (int k0 = 0; k0 < K; k0 += KC) {
        #pragma unroll
        for (int i = t; i < KC * 64 / 4; i += 256)
            ((float4*)Ws)[i] = ((const float4*)(W + k0 * 64))[i];
        #pragma unroll
        for (int i = t; i < 32 * KC / 4; i += 256) {
            int r = i / (KC / 4);
            int c = (i % (KC / 4)) * 4;
            int gr = row0 + r;
            float4 x = {0.f, 0.f, 0.f, 0.f};
            if (gr < n) x = *(const float4*)(X + (size_t)gr * K + k0 + c);
            float2* p = &Xd[r * XSTR + c];
            p[0] = make_float2(x.x, x.x); p[1] = make_float2(x.y, x.y);
            p[2] = make_float2(x.z, x.z); p[3] = make_float2(x.w, x.w);
        }
        __syncthreads();

        #pragma unroll
        for (int k = 0; k < KC; k++) {
            ulonglong2 w = *reinterpret_cast<const ulonglong2*>(&Ws[k * 64 + tix * 4]);
            unsigned long long x0 = *reinterpret_cast<const unsigned long long*>(&Xd[(tiy * 2 + 0) * XSTR + k]);
            unsigned long long x1 = *reinterpret_cast<const unsigned long long*>(&Xd[(tiy * 2 + 1) * XSTR + k]);
            asm("fma.rn.f32x2 %0, %1, %2, %0;" : "+l"(acc[0][0]) : "l"(x0), "l"(w.x));
            asm("fma.rn.f32x2 %0, %1, %2, %0;" : "+l"(acc[0][1]) : "l"(x0), "l"(w.y));
            asm("fma.rn.f32x2 %0, %1, %2, %0;" : "+l"(acc[1][0]) : "l"(x1), "l"(w.x));
            asm("fma.rn.f32x2 %0, %1, %2, %0;" : "+l"(acc[1][1]) : "l"(x1), "l"(w.y));
        }
        __syncthreads();
    }

    float4 b4 = *(const float4*)(B + tix * 4);
    #pragma unroll
    for (int r = 0; r < 2; r++) {
        int gr = row0 + tiy * 2 + r;
        if (gr >= n) continue;
        float o0 = __uint_as_float((unsigned)(acc[r][0] & 0xffffffffu)) + b4.x;
        float o1 = __uint_as_float((unsigned)(acc[r][0] >> 32))         + b4.y;
        float o2 = __uint_as_float((unsigned)(acc[r][1] & 0xffffffffu)) + b4.z;
        float o3 = __uint_as_float((unsigned)(acc[r][1] >> 32))         + b4.w;
        __half2 h01 = __floats2half2_rn(o0, o1);
        __half2 h23 = __floats2half2_rn(o2, o3);
        uint2 pk = make_uint2(*(unsigned*)&h01, *(unsigned*)&h23);
        *(uint2*)(u + (size_t)gr * 64 + tix * 4) = pk;
    }
}

// ---------------------------------------------------------------------------
// Aggregate node v (8 lanes, lane h): out = relu(sum + self*sv) * dis[v].
// Unroll 4 with 4 independent fp16 accumulator sets (per-thread MLP=4).
// WEIGHTED: messages scaled by dish[src] via HFMA2; self scaled by dis[v].
// ---------------------------------------------------------------------------
template<bool WEIGHTED>
__device__ __forceinline__ void aggregate_node(
    int v, int h,
    const int* __restrict__ rowptr, const int* __restrict__ deg,
    const int* __restrict__ colidx, const float* __restrict__ dis,
    const __half* __restrict__ dish, const __half* __restrict__ u,
    float out[8])
{
    const uint4* uv = (const uint4*)u;
    const __half2 z = __float2half2_rn(0.f);
    __half2 s[4][4];
    #pragma unroll
    for (int a = 0; a < 4; a++)
        #pragma unroll
        for (int k = 0; k < 4; k++) s[a][k] = z;

    int p0 = __ldg(rowptr + v);
    int d  = __ldg(deg + v);

    int j = 0;
    for (; j + 4 <= d; j += 4) {
        int c0 = __ldg(colidx + p0 + j);
        int c1 = __ldg(colidx + p0 + j + 1);
        int c2 = __ldg(colidx + p0 + j + 2);
        int c3 = __ldg(colidx + p0 + j + 3);
        uint4 x0 = __ldg(uv + (size_t)c0 * 8 + h);
        uint4 x1 = __ldg(uv + (size_t)c1 * 8 + h);
        uint4 x2 = __ldg(uv + (size_t)c2 * 8 + h);
        uint4 x3 = __ldg(uv + (size_t)c3 * 8 + h);
        if (WEIGHTED) {
            __half2 w0 = __half2half2(__ldg(dish + c0));
            __half2 w1 = __half2half2(__ldg(dish + c1));
            __half2 w2 = __half2half2(__ldg(dish + c2));
            __half2 w3 = __half2half2(__ldg(dish + c3));
            #pragma unroll
            for (int k = 0; k < 4; k++) {
                s[0][k] = __hfma2(w0, ((__half2*)&x0)[k], s[0][k]);
                s[1][k] = __hfma2(w1, ((__half2*)&x1)[k], s[1][k]);
                s[2][k] = __hfma2(w2, ((__half2*)&x2)[k], s[2][k]);
                s[3][k] = __hfma2(w3, ((__half2*)&x3)[k], s[3][k]);
            }
        } else {
            #pragma unroll
            for (int k = 0; k < 4; k++) {
                s[0][k] = __hadd2(s[0][k], ((__half2*)&x0)[k]);
                s[1][k] = __hadd2(s[1][k], ((__half2*)&x1)[k]);
                s[2][k] = __hadd2(s[2][k], ((__half2*)&x2)[k]);
                s[3][k] = __hadd2(s[3][k], ((__half2*)&x3)[k]);
            }
        }
    }
    for (; j < d; j++) {
        int c0 = __ldg(colidx + p0 + j);
        uint4 x0 = __ldg(uv + (size_t)c0 * 8 + h);
        if (WEIGHTED) {
            __half2 w0 = __half2half2(__ldg(dish + c0));
            #pragma unroll
            for (int k = 0; k < 4; k++)
                s[0][k] = __hfma2(w0, ((__half2*)&x0)[k], s[0][k]);
        } else {
            #pragma unroll
            for (int k = 0; k < 4; k++)
                s[0][k] = __hadd2(s[0][k], ((__half2*)&x0)[k]);
        }
    }

    uint4 ps = __ldg(uv + (size_t)v * 8 + h);
    float dv = __ldg(dis + v);
    float sv = WEIGHTED ? dv : 1.f;

    #pragma unroll
    for (int k = 0; k < 4; k++) {
        float2 f0 = __half22float2(s[0][k]);
        float2 f1 = __half22float2(s[1][k]);
        float2 f2 = __half22float2(s[2][k]);
        float2 f3 = __half22float2(s[3][k]);
        float2 fs = __half22float2(((__half2*)&ps)[k]);
        float a0 = (f0.x + f1.x) + (f2.x + f3.x) + fs.x * sv;
        float a1 = (f0.y + f1.y) + (f2.y + f3.y) + fs.y * sv;
        out[k * 2 + 0] = fmaxf(a0, 0.f) * dv;
        out[k * 2 + 1] = fmaxf(a1, 0.f) * dv;
    }
}

// ---------------------------------------------------------------------------
// Fused pull + GEMM64.
// ---------------------------------------------------------------------------
template<bool WEIGHTED>
__global__ void fused64_kernel(const int* __restrict__ rowptr,
                               const int* __restrict__ deg,
                               const int* __restrict__ colidx,
                               const float* __restrict__ dis,
                               const __half* __restrict__ dish,
                               const __half* __restrict__ u_in,
                               const float* __restrict__ W,
                               const float* __restrict__ B,
                               __half* __restrict__ u_out, int n) {
    constexpr int KC = 64;
    constexpr int XSTR = KC + 1;
    __shared__ float  Ws[KC * 64];
    __shared__ float2 Xd[32 * XSTR];

    int t = threadIdx.x;
    int row0 = blockIdx.x * 32;

    #pragma unroll
    for (int i = t; i < KC * 64 / 4; i += 256)
        ((float4*)Ws)[i] = ((const float4*)W)[i];

    // Phase 1: aggregate 32 nodes -> Xd (duplicated f32x2)
    {
        int r = t >> 3;
        int h = t & 7;
        int v = row0 + r;
        float xv[8] = {0,0,0,0,0,0,0,0};
        if (v < n)
            aggregate_node<WEIGHTED>(v, h, rowptr, deg, colidx, dis, dish, u_in, xv);
        float2* p = &Xd[r * XSTR + h * 8];
        #pragma unroll
        for (int k = 0; k < 8; k++) p[k] = make_float2(xv[k], xv[k]);
    }
    __syncthreads();

    // Phase 2: 32x64 GEMM
    int tix = t & 15;
    int tiy = t >> 4;
    unsigned long long acc[2][2];
    acc[0][0] = acc[0][1] = acc[1][0] = acc[1][1] = 0ull;

    #pragma unroll
    for (int k = 0; k < KC; k++) {
        ulonglong2 w = *reinterpret_cast<const ulonglong2*>(&Ws[k * 64 + tix * 4]);
        unsigned long long x0 = *reinterpret_cast<const unsigned long long*>(&Xd[(tiy * 2 + 0) * XSTR + k]);
        unsigned long long x1 = *reinterpret_cast<const unsigned long long*>(&Xd[(tiy * 2 + 1) * XSTR + k]);
        asm("fma.rn.f32x2 %0, %1, %2, %0;" : "+l"(acc[0][0]) : "l"(x0), "l"(w.x));
        asm("fma.rn.f32x2 %0, %1, %2, %0;" : "+l"(acc[0][1]) : "l"(x0), "l"(w.y));
        asm("fma.rn.f32x2 %0, %1, %2, %0;" : "+l"(acc[1][0]) : "l"(x1), "l"(w.x));
        asm("fma.rn.f32x2 %0, %1, %2, %0;" : "+l"(acc[1][1]) : "l"(x1), "l"(w.y));
    }

    float4 b4 = *(const float4*)(B + tix * 4);
    #pragma unroll
    for (int r = 0; r < 2; r++) {
        int gr = row0 + tiy * 2 + r;
        if (gr >= n) continue;
        float s = __ldg(dis + gr);
        float o0 = (__uint_as_float((unsigned)(acc[r][0] & 0xffffffffu)) + b4.x) * s;
        float o1 = (__uint_as_float((unsigned)(acc[r][0] >> 32))         + b4.y) * s;
        float o2 = (__uint_as_float((unsigned)(acc[r][1] & 0xffffffffu)) + b4.z) * s;
        float o3 = (__uint_as_float((unsigned)(acc[r][1] >> 32))         + b4.w) * s;
        __half2 h01 = __floats2half2_rn(o0, o1);
        __half2 h23 = __floats2half2_rn(o2, o3);
        uint2 pk = make_uint2(*(unsigned*)&h01, *(unsigned*)&h23);
        *(uint2*)(u_out + (size_t)gr * 64 + tix * 4) = pk;
    }
}

// ---------------------------------------------------------------------------
// Fused pull + head GEMM (K=64, NOUT=40), fp32 output.
// ---------------------------------------------------------------------------
__global__ void fused_head_kernel(const int* __restrict__ rowptr,
                                  const int* __restrict__ deg,
                                  const int* __restrict__ colidx,
                                  const float* __restrict__ dis,
                                  const __half* __restrict__ dish,
                                  const __half* __restrict__ u_in,
                                  const float* __restrict__ W,
                                  const float* __restrict__ B,
                                  float* __restrict__ out, int n) {
    constexpr int K = HID, NOUT = OUTD;
    __shared__ float Ws[K * NOUT];
    __shared__ float Xs[32 * K];

    int t = threadIdx.x;
    int row0 = blockIdx.x * 32;

    #pragma unroll 4
    for (int i = t; i < K * NOUT; i += 256) Ws[i] = W[i];

    {
        int r = t >> 3;
        int h = t & 7;
        int v = row0 + r;
        float xv[8] = {0,0,0,0,0,0,0,0};
        if (v < n)
            aggregate_node<false>(v, h, rowptr, deg, colidx, dis, dish, u_in, xv);
        float* p = &Xs[r * K + h * 8];
        #pragma unroll
        for (int k = 0; k < 8; k++) p[k] = xv[k];
    }
    __syncthreads();

    int warp = t >> 5, lane = t & 31;
    int r0 = warp * 4;
    float acc0[4] = {0.f, 0.f, 0.f, 0.f};
    float acc1[4] = {0.f, 0.f, 0.f, 0.f};

    #pragma unroll
    for (int k = 0; k < K; k++) {
        float w0 = Ws[k * NOUT + lane];
        float w1 = (lane + 32 < NOUT) ? Ws[k * NOUT + lane + 32] : 0.f;
        #pragma unroll
        for (int r = 0; r < 4; r++) {
            float xv = Xs[(r0 + r) * K + k];
            acc0[r] = fmaf(xv, w0, acc0[r]);
            acc1[r] = fmaf(xv, w1, acc1[r]);
        }
    }

    float b0 = B[lane];
    float b1 = (lane + 32 < NOUT) ? B[lane + 32] : 0.f;
    #pragma unroll
    for (int r = 0; r < 4; r++) {
        int gr = row0 + r0 + r;
        if (gr >= n) continue;
        out[(size_t)gr * NOUT + lane] = acc0[r] + b0;
        if (lane + 32 < NOUT) out[(size_t)gr * NOUT + lane + 32] = acc1[r] + b1;
    }
}

// ---------------------------------------------------------------------------
extern "C" void kernel_launch(void* const* d_in, const int* in_sizes, int n_in,
                              void* d_out, int out_size) {
    const float* x    = (const float*)d_in[0];
    const int*   ei   = (const int*)d_in[1];
    const float* W0   = (const float*)d_in[2];
    const float* b0   = (const float*)d_in[3];
    const float* W1   = (const float*)d_in[4];
    const float* b1   = (const float*)d_in[5];
    const float* W2   = (const float*)d_in[6];
    const float* b2   = (const float*)d_in[7];
    const float* Wout = (const float*)d_in[8];
    const float* bout = (const float*)d_in[9];
    float* out = (float*)d_out;

    const int N = in_sizes[0] / F_IN;
    const int E = in_sizes[1] / 2;
    const int* src = ei;
    const int* dst = ei + E;

    __half *uA, *uB, *dish;
    float *dis;
    int *deg, *rowptr, *cursor, *colidx, *bsum;
    cudaGetSymbolAddress((void**)&uA,     g_uA);
    cudaGetSymbolAddress((void**)&uB,     g_uB);
    cudaGetSymbolAddress((void**)&deg,    g_deg);
    cudaGetSymbolAddress((void**)&dis,    g_dis);
    cudaGetSymbolAddress((void**)&dish,   g_dish);
    cudaGetSymbolAddress((void**)&rowptr, g_rowptr);
    cudaGetSymbolAddress((void**)&cursor, g_cursor);
    cudaGetSymbolAddress((void**)&colidx, g_colidx);
    cudaGetSymbolAddress((void**)&bsum,   g_bsum);

    const int TPB = 256;
    int gemmBlocks = (N + 31) / 32;
    int countBlocks = 2048;
    dim3 fused0_grid(gemmBlocks + countBlocks);
    dim3 layer_grid(gemmBlocks);
    int nscan = (N + 1023) / 1024;

    // 1: memset, 2: layer-0 GEMM + degree count
    cudaMemsetAsync(deg, 0, N * sizeof(int), 0);
    gemm0_kernel<<<fused0_grid, TPB>>>(x, W0, b0, uA, N, dst, E, deg, gemmBlocks);

    // 3-5: CSR build + dis tables (scan2 folded into scan3)
    scan1_kernel<<<nscan, 256>>>(deg, rowptr, dis, dish, bsum, N);
    scan3_kernel<<<(N + TPB - 1) / TPB, TPB>>>(bsum, rowptr, cursor, N, nscan);
    scatter_kernel<<<(E + TPB - 1) / TPB, TPB>>>(src, dst, cursor, colidx, E);

    // 6-8: fused layers (launch #6 = fused64<true> — ncu -s 5 capture slot)
    fused64_kernel<true><<<layer_grid, TPB>>>(rowptr, deg, colidx, dis, dish, uA, W1, b1, uB, N);
    fused64_kernel<false><<<layer_grid, TPB>>>(rowptr, deg, colidx, dis, dish, uB, W2, b2, uA, N);
    fused_head_kernel<<<layer_grid, TPB>>>(rowptr, deg, colidx, dis, dish, uA, Wout, bout, out, N);
}

// round 10
// speedup vs baseline: 1.0596x; 1.0422x over previous
#include <cuda_runtime.h>
#include <cuda_fp16.h>
#include <cstdint>

#define NN   100000
#define EE   1600000
#define F_IN 128
#define HID  64
#define OUTD 40

// Scratch (device globals — allocation is forbidden)
__device__ __half g_uA[NN * HID];
__device__ __half g_uB[NN * HID];
__device__ int    g_deg[NN];
__device__ float  g_dis[NN];
__device__ __half g_dish[NN];
__device__ int    g_rowptr[NN];
__device__ int    g_cursor[NN];
__device__ int    g_colidx[EE];
__device__ int    g_bsum[128];

// ---------------------------------------------------------------------------
// Degree histogram (standalone so the CSR scan chain can start immediately;
// the edge scatter then overlaps the layer-0 GEMM).
// ---------------------------------------------------------------------------
__global__ void count_deg_kernel(const int* __restrict__ dst, int E, int* __restrict__ deg) {
    int e = blockIdx.x * blockDim.x + threadIdx.x;
    if (e < E) atomicAdd(&deg[dst[e]], 1);
}

// ---------------------------------------------------------------------------
// scan1: per-1024-chunk exclusive scan of deg -> rowptr + dis/dish tables
// ---------------------------------------------------------------------------
__global__ void scan1_kernel(const int* __restrict__ deg, int* __restrict__ rowptr,
                             float* __restrict__ dis, __half* __restrict__ dish,
                             int* __restrict__ bsum, int n) {
    __shared__ int sh[256];
    int t = threadIdx.x;
    int base = blockIdx.x * 1024 + t * 4;
    int v[4]; int s = 0;
    #pragma unroll
    for (int j = 0; j < 4; j++) {
        v[j] = (base + j < n) ? deg[base + j] : 0;
        if (base + j < n) {
            float r = rsqrtf((float)(v[j] + 1));
            dis[base + j] = r;
            dish[base + j] = __float2half_rn(r);
        }
        s += v[j];
    }
    sh[t] = s;
    for (int off = 1; off < 256; off <<= 1) {
        __syncthreads();
        int x = (t >= off) ? sh[t - off] : 0;
        __syncthreads();
        sh[t] += x;
    }
    __syncthreads();
    int excl = sh[t] - s;
    int run = 0;
    #pragma unroll
    for (int j = 0; j < 4; j++) {
        if (base + j < n) rowptr[base + j] = excl + run;
        run += v[j];
    }
    if (t == 255) bsum[blockIdx.x] = sh[255];
}

// ---------------------------------------------------------------------------
// scan3: finalize rowptr/cursor; each block computes the bsum prefix itself
// (nb <= 128 entries), absorbing the old scan2 kernel.
// ---------------------------------------------------------------------------
__global__ void scan3_kernel(const int* __restrict__ bsum, int* __restrict__ rowptr,
                             int* __restrict__ cursor, int n, int nb) {
    __shared__ int sh[128];
    int t = threadIdx.x;
    if (t < 128) sh[t] = (t < nb) ? bsum[t] : 0;
    __syncthreads();
    for (int off = 1; off < 128; off <<= 1) {
        int x = (t < 128 && t >= off) ? sh[t - off] : 0;
        __syncthreads();
        if (t < 128) sh[t] += x;
        __syncthreads();
    }
    int i = blockIdx.x * blockDim.x + t;
    if (i < n) {
        int c = i >> 10;
        int excl = (c == 0) ? 0 : sh[c - 1];
        int r = rowptr[i] + excl;
        rowptr[i] = r;
        cursor[i] = r;
    }
}

// ---------------------------------------------------------------------------
// Heterogeneous mega kernel:
//   blocks [0, gemmBlocks):  layer-0 GEMM  X[n,128] @ W0 + b0 -> uA fp16
//   blocks [gemmBlocks, +scatB): CSR edge scatter (independent outputs)
// ---------------------------------------------------------------------------
__global__ void gemm0_scatter_kernel(const float* __restrict__ X,
                                     const float* __restrict__ W,
                                     const float* __restrict__ B,
                                     __half* __restrict__ u, int n,
                                     const int* __restrict__ src,
                                     const int* __restrict__ dst,
                                     int* __restrict__ cursor,
                                     int* __restrict__ colidx, int E,
                                     int gemmBlocks) {
    constexpr int K = F_IN;
    constexpr int KC = 64;
    constexpr int XSTR = KC + 1;
    __shared__ float  Ws[KC * 64];
    __shared__ float2 Xd[32 * XSTR];

    int t = threadIdx.x;

    if ((int)blockIdx.x >= gemmBlocks) {
        int e = (blockIdx.x - gemmBlocks) * 256 + t;
        if (e < E) {
            int p = atomicAdd(&cursor[dst[e]], 1);
            colidx[p] = src[e];
        }
        return;
    }

    int row0 = blockIdx.x * 32;
    int tix = t & 15;
    int tiy = t >> 4;

    unsigned long long acc[2][2];
    acc[0][0] = acc[0][1] = acc[1][0] = acc[1][1] = 0ull;

    for (int k0 = 0; k0 < K; k0 += KC) {
        #pragma unroll
        for (int i = t; i < KC * 64 / 4; i += 256)
            ((float4*)Ws)[i] = ((const float4*)(W + k0 * 64))[i];
        #pragma unroll
        for (int i = t; i < 32 * KC / 4; i += 256) {
            int r = i / (KC / 4);
            int c = (i % (KC / 4)) * 4;
            int gr = row0 + r;
            float4 x = {0.f, 0.f, 0.f, 0.f};
            if (gr < n) x = *(const float4*)(X + (size_t)gr * K + k0 + c);
            float2* p = &Xd[r * XSTR + c];
            p[0] = make_float2(x.x, x.x); p[1] = make_float2(x.y, x.y);
            p[2] = make_float2(x.z, x.z); p[3] = make_float2(x.w, x.w);
        }
        __syncthreads();

        #pragma unroll
        for (int k = 0; k < KC; k++) {
            ulonglong2 w = *reinterpret_cast<const ulonglong2*>(&Ws[k * 64 + tix * 4]);
            unsigned long long x0 = *reinterpret_cast<const unsigned long long*>(&Xd[(tiy * 2 + 0) * XSTR + k]);
            unsigned long long x1 = *reinterpret_cast<const unsigned long long*>(&Xd[(tiy * 2 + 1) * XSTR + k]);
            asm("fma.rn.f32x2 %0, %1, %2, %0;" : "+l"(acc[0][0]) : "l"(x0), "l"(w.x));
            asm("fma.rn.f32x2 %0, %1, %2, %0;" : "+l"(acc[0][1]) : "l"(x0), "l"(w.y));
            asm("fma.rn.f32x2 %0, %1, %2, %0;" : "+l"(acc[1][0]) : "l"(x1), "l"(w.x));
            asm("fma.rn.f32x2 %0, %1, %2, %0;" : "+l"(acc[1][1]) : "l"(x1), "l"(w.y));
        }
        __syncthreads();
    }

    float4 b4 = *(const float4*)(B + tix * 4);
    #pragma unroll
    for (int r = 0; r < 2; r++) {
        int gr = row0 + tiy * 2 + r;
        if (gr >= n) continue;
        float o0 = __uint_as_float((unsigned)(acc[r][0] & 0xffffffffu)) + b4.x;
        float o1 = __uint_as_float((unsigned)(acc[r][0] >> 32))         + b4.y;
        float o2 = __uint_as_float((unsigned)(acc[r][1] & 0xffffffffu)) + b4.z;
        float o3 = __uint_as_float((unsigned)(acc[r][1] >> 32))         + b4.w;
        __half2 h01 = __floats2half2_rn(o0, o1);
        __half2 h23 = __floats2half2_rn(o2, o3);
        uint2 pk = make_uint2(*(unsigned*)&h01, *(unsigned*)&h23);
        *(uint2*)(u + (size_t)gr * 64 + tix * 4) = pk;
    }
}

// ---------------------------------------------------------------------------
// Aggregate node v (8 lanes, lane h): out = relu(sum + self*sv) * dis[v].
// R6 form: unroll 2, two fp16 accumulator sets; fp32 combine.
// ---------------------------------------------------------------------------
template<bool WEIGHTED>
__device__ __forceinline__ void aggregate_node(
    int v, int h,
    const int* __restrict__ rowptr, const int* __restrict__ deg,
    const int* __restrict__ colidx, const float* __restrict__ dis,
    const __half* __restrict__ dish, const __half* __restrict__ u,
    float out[8])
{
    const uint4* uv = (const uint4*)u;
    const __half2 z = __float2half2_rn(0.f);
    __half2 s0[4] = {z, z, z, z};
    __half2 s1[4] = {z, z, z, z};

    int p0 = __ldg(rowptr + v);
    int d  = __ldg(deg + v);

    int j = 0;
    for (; j + 2 <= d; j += 2) {
        int c0 = __ldg(colidx + p0 + j);
        int c1 = __ldg(colidx + p0 + j + 1);
        uint4 x0 = __ldg(uv + (size_t)c0 * 8 + h);
        uint4 x1 = __ldg(uv + (size_t)c1 * 8 + h);
        if (WEIGHTED) {
            __half2 w0 = __half2half2(__ldg(dish + c0));
            __half2 w1 = __half2half2(__ldg(dish + c1));
            #pragma unroll
            for (int k = 0; k < 4; k++) {
                s0[k] = __hfma2(w0, ((__half2*)&x0)[k], s0[k]);
                s1[k] = __hfma2(w1, ((__half2*)&x1)[k], s1[k]);
            }
        } else {
            #pragma unroll
            for (int k = 0; k < 4; k++) {
                s0[k] = __hadd2(s0[k], ((__half2*)&x0)[k]);
                s1[k] = __hadd2(s1[k], ((__half2*)&x1)[k]);
            }
        }
    }
    if (j < d) {
        int c0 = __ldg(colidx + p0 + j);
        uint4 x0 = __ldg(uv + (size_t)c0 * 8 + h);
        if (WEIGHTED) {
            __half2 w0 = __half2half2(__ldg(dish + c0));
            #pragma unroll
            for (int k = 0; k < 4; k++)
                s0[k] = __hfma2(w0, ((__half2*)&x0)[k], s0[k]);
        } else {
            #pragma unroll
            for (int k = 0; k < 4; k++)
                s0[k] = __hadd2(s0[k], ((__half2*)&x0)[k]);
        }
    }

    uint4 ps = __ldg(uv + (size_t)v * 8 + h);
    float dv = __ldg(dis + v);
    float sv = WEIGHTED ? dv : 1.f;

    #pragma unroll
    for (int k = 0; k < 4; k++) {
        float2 f0 = __half22float2(s0[k]);
        float2 f1 = __half22float2(s1[k]);
        float2 fs = __half22float2(((__half2*)&ps)[k]);
        float a0 = f0.x + f1.x + fs.x * sv;
        float a1 = f0.y + f1.y + fs.y * sv;
        out[k * 2 + 0] = fmaxf(a0, 0.f) * dv;
        out[k * 2 + 1] = fmaxf(a1, 0.f) * dv;
    }
}

// ---------------------------------------------------------------------------
// Fused pull + GEMM64.
// ---------------------------------------------------------------------------
template<bool WEIGHTED>
__global__ void fused64_kernel(const int* __restrict__ rowptr,
                               const int* __restrict__ deg,
                               const int* __restrict__ colidx,
                               const float* __restrict__ dis,
                               const __half* __restrict__ dish,
                               const __half* __restrict__ u_in,
                               const float* __restrict__ W,
                               const float* __restrict__ B,
                               __half* __restrict__ u_out, int n) {
    constexpr int KC = 64;
    constexpr int XSTR = KC + 1;
    __shared__ float  Ws[KC * 64];
    __shared__ float2 Xd[32 * XSTR];

    int t = threadIdx.x;
    int row0 = blockIdx.x * 32;

    #pragma unroll
    for (int i = t; i < KC * 64 / 4; i += 256)
        ((float4*)Ws)[i] = ((const float4*)W)[i];

    // Phase 1: aggregate 32 nodes -> Xd (duplicated f32x2)
    {
        int r = t >> 3;
        int h = t & 7;
        int v = row0 + r;
        float xv[8] = {0,0,0,0,0,0,0,0};
        if (v < n)
            aggregate_node<WEIGHTED>(v, h, rowptr, deg, colidx, dis, dish, u_in, xv);
        float2* p = &Xd[r * XSTR + h * 8];
        #pragma unroll
        for (int k = 0; k < 8; k++) p[k] = make_float2(xv[k], xv[k]);
    }
    __syncthreads();

    // Phase 2: 32x64 GEMM
    int tix = t & 15;
    int tiy = t >> 4;
    unsigned long long acc[2][2];
    acc[0][0] = acc[0][1] = acc[1][0] = acc[1][1] = 0ull;

    #pragma unroll
    for (int k = 0; k < KC; k++) {
        ulonglong2 w = *reinterpret_cast<const ulonglong2*>(&Ws[k * 64 + tix * 4]);
        unsigned long long x0 = *reinterpret_cast<const unsigned long long*>(&Xd[(tiy * 2 + 0) * XSTR + k]);
        unsigned long long x1 = *reinterpret_cast<const unsigned long long*>(&Xd[(tiy * 2 + 1) * XSTR + k]);
        asm("fma.rn.f32x2 %0, %1, %2, %0;" : "+l"(acc[0][0]) : "l"(x0), "l"(w.x));
        asm("fma.rn.f32x2 %0, %1, %2, %0;" : "+l"(acc[0][1]) : "l"(x0), "l"(w.y));
        asm("fma.rn.f32x2 %0, %1, %2, %0;" : "+l"(acc[1][0]) : "l"(x1), "l"(w.x));
        asm("fma.rn.f32x2 %0, %1, %2, %0;" : "+l"(acc[1][1]) : "l"(x1), "l"(w.y));
    }

    float4 b4 = *(const float4*)(B + tix * 4);
    #pragma unroll
    for (int r = 0; r < 2; r++) {
        int gr = row0 + tiy * 2 + r;
        if (gr >= n) continue;
        float s = __ldg(dis + gr);
        float o0 = (__uint_as_float((unsigned)(acc[r][0] & 0xffffffffu)) + b4.x) * s;
        float o1 = (__uint_as_float((unsigned)(acc[r][0] >> 32))         + b4.y) * s;
        float o2 = (__uint_as_float((unsigned)(acc[r][1] & 0xffffffffu)) + b4.z) * s;
        float o3 = (__uint_as_float((unsigned)(acc[r][1] >> 32))         + b4.w) * s;
        __half2 h01 = __floats2half2_rn(o0, o1);
        __half2 h23 = __floats2half2_rn(o2, o3);
        uint2 pk = make_uint2(*(unsigned*)&h01, *(unsigned*)&h23);
        *(uint2*)(u_out + (size_t)gr * 64 + tix * 4) = pk;
    }
}

// ---------------------------------------------------------------------------
// Fused pull + head GEMM (K=64, NOUT=40), fp32 output.
// ---------------------------------------------------------------------------
__global__ void fused_head_kernel(const int* __restrict__ rowptr,
                                  const int* __restrict__ deg,
                                  const int* __restrict__ colidx,
                                  const float* __restrict__ dis,
                                  const __half* __restrict__ dish,
                                  const __half* __restrict__ u_in,
                                  const float* __restrict__ W,
                                  const float* __restrict__ B,
                                  float* __restrict__ out, int n) {
    constexpr int K = HID, NOUT = OUTD;
    __shared__ float Ws[K * NOUT];
    __shared__ float Xs[32 * K];

    int t = threadIdx.x;
    int row0 = blockIdx.x * 32;

    #pragma unroll 4
    for (int i = t; i < K * NOUT; i += 256) Ws[i] = W[i];

    {
        int r = t >> 3;
        int h = t & 7;
        int v = row0 + r;
        float xv[8] = {0,0,0,0,0,0,0,0};
        if (v < n)
            aggregate_node<false>(v, h, rowptr, deg, colidx, dis, dish, u_in, xv);
        float* p = &Xs[r * K + h * 8];
        #pragma unroll
        for (int k = 0; k < 8; k++) p[k] = xv[k];
    }
    __syncthreads();

    int warp = t >> 5, lane = t & 31;
    int r0 = warp * 4;
    float acc0[4] = {0.f, 0.f, 0.f, 0.f};
    float acc1[4] = {0.f, 0.f, 0.f, 0.f};

    #pragma unroll
    for (int k = 0; k < K; k++) {
        float w0 = Ws[k * NOUT + lane];
        float w1 = (lane + 32 < NOUT) ? Ws[k * NOUT + lane + 32] : 0.f;
        #pragma unroll
        for (int r = 0; r < 4; r++) {
            float xv = Xs[(r0 + r) * K + k];
            acc0[r] = fmaf(xv, w0, acc0[r]);
            acc1[r] = fmaf(xv, w1, acc1[r]);
        }
    }

    float b0 = B[lane];
    float b1 = (lane + 32 < NOUT) ? B[lane + 32] : 0.f;
    #pragma unroll
    for (int r = 0; r < 4; r++) {
        int gr = row0 + r0 + r;
        if (gr >= n) continue;
        out[(size_t)gr * NOUT + lane] = acc0[r] + b0;
        if (lane + 32 < NOUT) out[(size_t)gr * NOUT + lane + 32] = acc1[r] + b1;
    }
}

// ---------------------------------------------------------------------------
extern "C" void kernel_launch(void* const* d_in, const int* in_sizes, int n_in,
                              void* d_out, int out_size) {
    const float* x    = (const float*)d_in[0];
    const int*   ei   = (const int*)d_in[1];
    const float* W0   = (const float*)d_in[2];
    const float* b0   = (const float*)d_in[3];
    const float* W1   = (const float*)d_in[4];
    const float* b1   = (const float*)d_in[5];
    const float* W2   = (const float*)d_in[6];
    const float* b2   = (const float*)d_in[7];
    const float* Wout = (const float*)d_in[8];
    const float* bout = (const float*)d_in[9];
    float* out = (float*)d_out;

    const int N = in_sizes[0] / F_IN;
    const int E = in_sizes[1] / 2;
    const int* src = ei;
    const int* dst = ei + E;

    __half *uA, *uB, *dish;
    float *dis;
    int *deg, *rowptr, *cursor, *colidx, *bsum;
    cudaGetSymbolAddress((void**)&uA,     g_uA);
    cudaGetSymbolAddress((void**)&uB,     g_uB);
    cudaGetSymbolAddress((void**)&deg,    g_deg);
    cudaGetSymbolAddress((void**)&dis,    g_dis);
    cudaGetSymbolAddress((void**)&dish,   g_dish);
    cudaGetSymbolAddress((void**)&rowptr, g_rowptr);
    cudaGetSymbolAddress((void**)&cursor, g_cursor);
    cudaGetSymbolAddress((void**)&colidx, g_colidx);
    cudaGetSymbolAddress((void**)&bsum,   g_bsum);

    const int TPB = 256;
    int gemmBlocks = (N + 31) / 32;                 // 3125
    int scatB = (E + TPB - 1) / TPB;                // 6250
    dim3 mega_grid(gemmBlocks + scatB);
    dim3 layer_grid(gemmBlocks);
    int nscan = (N + 1023) / 1024;

    // CSR prerequisite chain (degree -> rowptr/cursor)
    cudaMemsetAsync(deg, 0, N * sizeof(int), 0);
    count_deg_kernel<<<(E + TPB - 1) / TPB, TPB>>>(dst, E, deg);
    scan1_kernel<<<nscan, 256>>>(deg, rowptr, dis, dish, bsum, N);
    scan3_kernel<<<(N + TPB - 1) / TPB, TPB>>>(bsum, rowptr, cursor, N, nscan);

    // Layer-0 GEMM overlapped with CSR edge scatter (independent outputs)
    gemm0_scatter_kernel<<<mega_grid, TPB>>>(x, W0, b0, uA, N,
                                             src, dst, cursor, colidx, E, gemmBlocks);

    // Fused layers
    fused64_kernel<true><<<layer_grid, TPB>>>(rowptr, deg, colidx, dis, dish, uA, W1, b1, uB, N);
    fused64_kernel<false><<<layer_grid, TPB>>>(rowptr, deg, colidx, dis, dish, uB, W2, b2, uA, N);
    fused_head_kernel<<<layer_grid, TPB>>>(rowptr, deg, colidx, dis, dish, uA, Wout, bout, out, N);
}

// round 11
// speedup vs baseline: 1.4193x; 1.3394x over previous
#include <cuda_runtime.h>
#include <cuda_fp16.h>
#include <cstdint>

#define NN   100000
#define EE   1600000
#define F_IN 128
#define HID  64
#define OUTD 40

// Scratch (device globals — allocation is forbidden)
__device__ __half g_uA[NN * HID];
__device__ __half g_uB[NN * HID];
__device__ int    g_deg[NN];
__device__ float  g_dis[NN];
__device__ __half g_dish[NN];
__device__ int    g_rowptr[NN];
__device__ int    g_cursor[NN];
__device__ int    g_colidx[EE];
__device__ int    g_bsum[128];

#define XSTR 68   // 64 rows + 4 pad (keeps 16B alignment of Xs[k] rows)

__device__ __forceinline__ unsigned long long pack2(float x) {
    unsigned long long r;
    asm("mov.b64 %0, {%1, %2};" : "=l"(r) : "f"(x), "f"(x));
    return r;
}

// ---------------------------------------------------------------------------
// Prep chain
// ---------------------------------------------------------------------------
__global__ void count_deg_kernel(const int* __restrict__ dst, int E, int* __restrict__ deg) {
    int e = blockIdx.x * blockDim.x + threadIdx.x;
    if (e < E) atomicAdd(&deg[dst[e]], 1);
}

__global__ void scan1_kernel(const int* __restrict__ deg, int* __restrict__ rowptr,
                             float* __restrict__ dis, __half* __restrict__ dish,
                             int* __restrict__ bsum, int n) {
    __shared__ int sh[256];
    int t = threadIdx.x;
    int base = blockIdx.x * 1024 + t * 4;
    int v[4]; int s = 0;
    #pragma unroll
    for (int j = 0; j < 4; j++) {
        v[j] = (base + j < n) ? deg[base + j] : 0;
        if (base + j < n) {
            float r = rsqrtf((float)(v[j] + 1));
            dis[base + j] = r;
            dish[base + j] = __float2half_rn(r);
        }
        s += v[j];
    }
    sh[t] = s;
    for (int off = 1; off < 256; off <<= 1) {
        __syncthreads();
        int x = (t >= off) ? sh[t - off] : 0;
        __syncthreads();
        sh[t] += x;
    }
    __syncthreads();
    int excl = sh[t] - s;
    int run = 0;
    #pragma unroll
    for (int j = 0; j < 4; j++) {
        if (base + j < n) rowptr[base + j] = excl + run;
        run += v[j];
    }
    if (t == 255) bsum[blockIdx.x] = sh[255];
}

__global__ void scan3_kernel(const int* __restrict__ bsum, int* __restrict__ rowptr,
                             int* __restrict__ cursor, int n, int nb) {
    __shared__ int sh[128];
    int t = threadIdx.x;
    if (t < 128) sh[t] = (t < nb) ? bsum[t] : 0;
    __syncthreads();
    for (int off = 1; off < 128; off <<= 1) {
        int x = (t < 128 && t >= off) ? sh[t - off] : 0;
        __syncthreads();
        if (t < 128) sh[t] += x;
        __syncthreads();
    }
    int i = blockIdx.x * blockDim.x + t;
    if (i < n) {
        int c = i >> 10;
        int excl = (c == 0) ? 0 : sh[c - 1];
        int r = rowptr[i] + excl;
        rowptr[i] = r;
        cursor[i] = r;
    }
}

// ---------------------------------------------------------------------------
// Layer-0 GEMM (64x64 block tile, thread 4x4, Xs k-major) + fused edge scatter.
// ---------------------------------------------------------------------------
__global__ void gemm0_scatter_kernel(const float* __restrict__ X,
                                     const float* __restrict__ W,
                                     const float* __restrict__ B,
                                     __half* __restrict__ u, int n,
                                     const int* __restrict__ src,
                                     const int* __restrict__ dst,
                                     int* __restrict__ cursor,
                                     int* __restrict__ colidx, int E,
                                     int gemmBlocks) {
    __shared__ float Ws[64 * 64];
    __shared__ float Xs[64 * XSTR];

    int t = threadIdx.x;

    if ((int)blockIdx.x >= gemmBlocks) {
        int e = (blockIdx.x - gemmBlocks) * 256 + t;
        if (e < E) {
            int p = atomicAdd(&cursor[dst[e]], 1);
            colidx[p] = src[e];
        }
        return;
    }

    int row0 = blockIdx.x * 64;
    int tix = t & 15;            // col group: cols tix*4..+3
    int tiy = t >> 4;            // row group: rows tiy*4..+3

    unsigned long long acc[4][2];
    #pragma unroll
    for (int r = 0; r < 4; r++) { acc[r][0] = 0ull; acc[r][1] = 0ull; }

    for (int k0 = 0; k0 < F_IN; k0 += 64) {
        // W chunk [64 k][64 cols]
        #pragma unroll
        for (int i = t; i < 64 * 64 / 4; i += 256)
            ((float4*)Ws)[i] = ((const float4*)(W + k0 * 64))[i];
        // X chunk, transposed to Xs[k][row]
        #pragma unroll
        for (int i = t; i < 64 * 16; i += 256) {
            int r = i >> 4;
            int c4 = (i & 15) * 4;
            int gr = row0 + r;
            float4 x = {0.f, 0.f, 0.f, 0.f};
            if (gr < n) x = *(const float4*)(X + (size_t)gr * F_IN + k0 + c4);
            Xs[(c4 + 0) * XSTR + r] = x.x;
            Xs[(c4 + 1) * XSTR + r] = x.y;
            Xs[(c4 + 2) * XSTR + r] = x.z;
            Xs[(c4 + 3) * XSTR + r] = x.w;
        }
        __syncthreads();

        #pragma unroll
        for (int k = 0; k < 64; k++) {
            ulonglong2 w = *reinterpret_cast<const ulonglong2*>(&Ws[k * 64 + tix * 4]);
            float4 xr = *reinterpret_cast<const float4*>(&Xs[k * XSTR + tiy * 4]);
            unsigned long long xp;
            xp = pack2(xr.x);
            asm("fma.rn.f32x2 %0, %1, %2, %0;" : "+l"(acc[0][0]) : "l"(xp), "l"(w.x));
            asm("fma.rn.f32x2 %0, %1, %2, %0;" : "+l"(acc[0][1]) : "l"(xp), "l"(w.y));
            xp = pack2(xr.y);
            asm("fma.rn.f32x2 %0, %1, %2, %0;" : "+l"(acc[1][0]) : "l"(xp), "l"(w.x));
            asm("fma.rn.f32x2 %0, %1, %2, %0;" : "+l"(acc[1][1]) : "l"(xp), "l"(w.y));
            xp = pack2(xr.z);
            asm("fma.rn.f32x2 %0, %1, %2, %0;" : "+l"(acc[2][0]) : "l"(xp), "l"(w.x));
            asm("fma.rn.f32x2 %0, %1, %2, %0;" : "+l"(acc[2][1]) : "l"(xp), "l"(w.y));
            xp = pack2(xr.w);
            asm("fma.rn.f32x2 %0, %1, %2, %0;" : "+l"(acc[3][0]) : "l"(xp), "l"(w.x));
            asm("fma.rn.f32x2 %0, %1, %2, %0;" : "+l"(acc[3][1]) : "l"(xp), "l"(w.y));
        }
        __syncthreads();
    }

    float4 b4 = *(const float4*)(B + tix * 4);
    #pragma unroll
    for (int r = 0; r < 4; r++) {
        int gr = row0 + tiy * 4 + r;
        if (gr >= n) continue;
        float o0 = __uint_as_float((unsigned)(acc[r][0] & 0xffffffffu)) + b4.x;
        float o1 = __uint_as_float((unsigned)(acc[r][0] >> 32))         + b4.y;
        float o2 = __uint_as_float((unsigned)(acc[r][1] & 0xffffffffu)) + b4.z;
        float o3 = __uint_as_float((unsigned)(acc[r][1] >> 32))         + b4.w;
        __half2 h01 = __floats2half2_rn(o0, o1);
        __half2 h23 = __floats2half2_rn(o2, o3);
        uint2 pk = make_uint2(*(unsigned*)&h01, *(unsigned*)&h23);
        *(uint2*)(u + (size_t)gr * 64 + tix * 4) = pk;
    }
}

// ---------------------------------------------------------------------------
// Aggregate node v with 4 lanes (lane h covers halfs [h*16, h*16+16)).
// Unroll 2, two fp16 accumulator sets; fp32 combine; out = relu(sum+self*sv)*dis[v].
// ---------------------------------------------------------------------------
template<bool WEIGHTED>
__device__ __forceinline__ void aggregate_node4(
    int v, int h,
    const int* __restrict__ rowptr, const int* __restrict__ deg,
    const int* __restrict__ colidx, const float* __restrict__ dis,
    const __half* __restrict__ dish, const __half* __restrict__ u,
    float out[16])
{
    const uint4* uv = (const uint4*)u;   // row stride = 8 uint4; lane h uses slots h*2, h*2+1
    const __half2 z = __float2half2_rn(0.f);
    __half2 s0[8], s1[8];
    #pragma unroll
    for (int k = 0; k < 8; k++) { s0[k] = z; s1[k] = z; }

    int p0 = __ldg(rowptr + v);
    int d  = __ldg(deg + v);
    int base = h * 2;

    int j = 0;
    for (; j + 2 <= d; j += 2) {
        int c0 = __ldg(colidx + p0 + j);
        int c1 = __ldg(colidx + p0 + j + 1);
        uint4 a0 = __ldg(uv + (size_t)c0 * 8 + base);
        uint4 a1 = __ldg(uv + (size_t)c0 * 8 + base + 1);
        uint4 b0 = __ldg(uv + (size_t)c1 * 8 + base);
        uint4 b1 = __ldg(uv + (size_t)c1 * 8 + base + 1);
        if (WEIGHTED) {
            __half2 w0 = __half2half2(__ldg(dish + c0));
            __half2 w1 = __half2half2(__ldg(dish + c1));
            #pragma unroll
            for (int k = 0; k < 4; k++) {
                s0[k]     = __hfma2(w0, ((__half2*)&a0)[k], s0[k]);
                s0[k + 4] = __hfma2(w0, ((__half2*)&a1)[k], s0[k + 4]);
                s1[k]     = __hfma2(w1, ((__half2*)&b0)[k], s1[k]);
                s1[k + 4] = __hfma2(w1, ((__half2*)&b1)[k], s1[k + 4]);
            }
        } else {
            #pragma unroll
            for (int k = 0; k < 4; k++) {
                s0[k]     = __hadd2(s0[k],     ((__half2*)&a0)[k]);
                s0[k + 4] = __hadd2(s0[k + 4], ((__half2*)&a1)[k]);
                s1[k]     = __hadd2(s1[k],     ((__half2*)&b0)[k]);
                s1[k + 4] = __hadd2(s1[k + 4], ((__half2*)&b1)[k]);
            }
        }
    }
    if (j < d) {
        int c0 = __ldg(colidx + p0 + j);
        uint4 a0 = __ldg(uv + (size_t)c0 * 8 + base);
        uint4 a1 = __ldg(uv + (size_t)c0 * 8 + base + 1);
        if (WEIGHTED) {
            __half2 w0 = __half2half2(__ldg(dish + c0));
            #pragma unroll
            for (int k = 0; k < 4; k++) {
                s0[k]     = __hfma2(w0, ((__half2*)&a0)[k], s0[k]);
                s0[k + 4] = __hfma2(w0, ((__half2*)&a1)[k], s0[k + 4]);
            }
        } else {
            #pragma unroll
            for (int k = 0; k < 4; k++) {
                s0[k]     = __hadd2(s0[k],     ((__half2*)&a0)[k]);
                s0[k + 4] = __hadd2(s0[k + 4], ((__half2*)&a1)[k]);
            }
        }
    }

    uint4 p0v = __ldg(uv + (size_t)v * 8 + base);
    uint4 p1v = __ldg(uv + (size_t)v * 8 + base + 1);
    float dv = __ldg(dis + v);
    float sv = WEIGHTED ? dv : 1.f;

    #pragma unroll
    for (int k = 0; k < 8; k++) {
        float2 f0 = __half22float2(s0[k]);
        float2 f1 = __half22float2(s1[k]);
        __half2 psk = (k < 4) ? ((__half2*)&p0v)[k] : ((__half2*)&p1v)[k - 4];
        float2 fs = __half22float2(psk);
        float a0 = f0.x + f1.x + fs.x * sv;
        float a1 = f0.y + f1.y + fs.y * sv;
        out[k * 2 + 0] = fmaxf(a0, 0.f) * dv;
        out[k * 2 + 1] = fmaxf(a1, 0.f) * dv;
    }
}

// ---------------------------------------------------------------------------
// Fused pull + GEMM64 (64-row block tile, thread 4x4, Xs k-major).
// ---------------------------------------------------------------------------
template<bool WEIGHTED>
__global__ void fused64_kernel(const int* __restrict__ rowptr,
                               const int* __restrict__ deg,
                               const int* __restrict__ colidx,
                               const float* __restrict__ dis,
                               const __half* __restrict__ dish,
                               const __half* __restrict__ u_in,
                               const float* __restrict__ W,
                               const float* __restrict__ B,
                               __half* __restrict__ u_out, int n) {
    __shared__ float Ws[64 * 64];
    __shared__ float Xs[64 * XSTR];

    int t = threadIdx.x;
    int row0 = blockIdx.x * 64;

    #pragma unroll
    for (int i = t; i < 64 * 64 / 4; i += 256)
        ((float4*)Ws)[i] = ((const float4*)W)[i];

    // Phase 1: aggregate 64 nodes (4 lanes each) -> Xs[k][row]
    {
        int r = t >> 2;
        int h = t & 3;
        int v = row0 + r;
        float xv[16];
        #pragma unroll
        for (int k = 0; k < 16; k++) xv[k] = 0.f;
        if (v < n)
            aggregate_node4<WEIGHTED>(v, h, rowptr, deg, colidx, dis, dish, u_in, xv);
        #pragma unroll
        for (int k = 0; k < 16; k++)
            Xs[(h * 16 + k) * XSTR + r] = xv[k];
    }
    __syncthreads();

    // Phase 2: 64x64 GEMM
    int tix = t & 15;
    int tiy = t >> 4;
    unsigned long long acc[4][2];
    #pragma unroll
    for (int r = 0; r < 4; r++) { acc[r][0] = 0ull; acc[r][1] = 0ull; }

    #pragma unroll
    for (int k = 0; k < 64; k++) {
        ulonglong2 w = *reinterpret_cast<const ulonglong2*>(&Ws[k * 64 + tix * 4]);
        float4 xr = *reinterpret_cast<const float4*>(&Xs[k * XSTR + tiy * 4]);
        unsigned long long xp;
        xp = pack2(xr.x);
        asm("fma.rn.f32x2 %0, %1, %2, %0;" : "+l"(acc[0][0]) : "l"(xp), "l"(w.x));
        asm("fma.rn.f32x2 %0, %1, %2, %0;" : "+l"(acc[0][1]) : "l"(xp), "l"(w.y));
        xp = pack2(xr.y);
        asm("fma.rn.f32x2 %0, %1, %2, %0;" : "+l"(acc[1][0]) : "l"(xp), "l"(w.x));
        asm("fma.rn.f32x2 %0, %1, %2, %0;" : "+l"(acc[1][1]) : "l"(xp), "l"(w.y));
        xp = pack2(xr.z);
        asm("fma.rn.f32x2 %0, %1, %2, %0;" : "+l"(acc[2][0]) : "l"(xp), "l"(w.x));
        asm("fma.rn.f32x2 %0, %1, %2, %0;" : "+l"(acc[2][1]) : "l"(xp), "l"(w.y));
        xp = pack2(xr.w);
        asm("fma.rn.f32x2 %0, %1, %2, %0;" : "+l"(acc[3][0]) : "l"(xp), "l"(w.x));
        asm("fma.rn.f32x2 %0, %1, %2, %0;" : "+l"(acc[3][1]) : "l"(xp), "l"(w.y));
    }

    float4 b4 = *(const float4*)(B + tix * 4);
    #pragma unroll
    for (int r = 0; r < 4; r++) {
        int gr = row0 + tiy * 4 + r;
        if (gr >= n) continue;
        float s = __ldg(dis + gr);
        float o0 = (__uint_as_float((unsigned)(acc[r][0] & 0xffffffffu)) + b4.x) * s;
        float o1 = (__uint_as_float((unsigned)(acc[r][0] >> 32))         + b4.y) * s;
        float o2 = (__uint_as_float((unsigned)(acc[r][1] & 0xffffffffu)) + b4.z) * s;
        float o3 = (__uint_as_float((unsigned)(acc[r][1] >> 32))         + b4.w) * s;
        __half2 h01 = __floats2half2_rn(o0, o1);
        __half2 h23 = __floats2half2_rn(o2, o3);
        uint2 pk = make_uint2(*(unsigned*)&h01, *(unsigned*)&h23);
        *(uint2*)(u_out + (size_t)gr * 64 + tix * 4) = pk;
    }
}

// ---------------------------------------------------------------------------
// Aggregate node v with 8 lanes (head kernel; R6 form).
// ---------------------------------------------------------------------------
__device__ __forceinline__ void aggregate_node8(
    int v, int h,
    const int* __restrict__ rowptr, const int* __restrict__ deg,
    const int* __restrict__ colidx, const float* __restrict__ dis,
    const __half* __restrict__ u,
    float out[8])
{
    const uint4* uv = (const uint4*)u;
    const __half2 z = __float2half2_rn(0.f);
    __half2 s0[4] = {z, z, z, z};
    __half2 s1[4] = {z, z, z, z};

    int p0 = __ldg(rowptr + v);
    int d  = __ldg(deg + v);

    int j = 0;
    for (; j + 2 <= d; j += 2) {
        int c0 = __ldg(colidx + p0 + j);
        int c1 = __ldg(colidx + p0 + j + 1);
        uint4 x0 = __ldg(uv + (size_t)c0 * 8 + h);
        uint4 x1 = __ldg(uv + (size_t)c1 * 8 + h);
        #pragma unroll
        for (int k = 0; k < 4; k++) {
            s0[k] = __hadd2(s0[k], ((__half2*)&x0)[k]);
            s1[k] = __hadd2(s1[k], ((__half2*)&x1)[k]);
        }
    }
    if (j < d) {
        int c0 = __ldg(colidx + p0 + j);
        uint4 x0 = __ldg(uv + (size_t)c0 * 8 + h);
        #pragma unroll
        for (int k = 0; k < 4; k++)
            s0[k] = __hadd2(s0[k], ((__half2*)&x0)[k]);
    }

    uint4 ps = __ldg(uv + (size_t)v * 8 + h);
    float dv = __ldg(dis + v);

    #pragma unroll
    for (int k = 0; k < 4; k++) {
        float2 f0 = __half22float2(s0[k]);
        float2 f1 = __half22float2(s1[k]);
        float2 fs = __half22float2(((__half2*)&ps)[k]);
        out[k * 2 + 0] = fmaxf(f0.x + f1.x + fs.x, 0.f) * dv;
        out[k * 2 + 1] = fmaxf(f0.y + f1.y + fs.y, 0.f) * dv;
    }
}

// ---------------------------------------------------------------------------
// Fused pull + head GEMM (K=64, NOUT=40), fp32 output. 32-row tile (unchanged).
// ---------------------------------------------------------------------------
__global__ void fused_head_kernel(const int* __restrict__ rowptr,
                                  const int* __restrict__ deg,
                                  const int* __restrict__ colidx,
                                  const float* __restrict__ dis,
                                  const __half* __restrict__ u_in,
                                  const float* __restrict__ W,
                                  const float* __restrict__ B,
                                  float* __restrict__ out, int n) {
    constexpr int K = HID, NOUT = OUTD;
    __shared__ float Ws[K * NOUT];
    __shared__ float Xs2[32 * K];

    int t = threadIdx.x;
    int row0 = blockIdx.x * 32;

    #pragma unroll 4
    for (int i = t; i < K * NOUT; i += 256) Ws[i] = W[i];

    {
        int r = t >> 3;
        int h = t & 7;
        int v = row0 + r;
        float xv[8] = {0,0,0,0,0,0,0,0};
        if (v < n)
            aggregate_node8(v, h, rowptr, deg, colidx, dis, u_in, xv);
        float* p = &Xs2[r * K + h * 8];
        #pragma unroll
        for (int k = 0; k < 8; k++) p[k] = xv[k];
    }
    __syncthreads();

    int warp = t >> 5, lane = t & 31;
    int r0 = warp * 4;
    float acc0[4] = {0.f, 0.f, 0.f, 0.f};
    float acc1[4] = {0.f, 0.f, 0.f, 0.f};

    #pragma unroll
    for (int k = 0; k < K; k++) {
        float w0 = Ws[k * NOUT + lane];
        float w1 = (lane + 32 < NOUT) ? Ws[k * NOUT + lane + 32] : 0.f;
        #pragma unroll
        for (int r = 0; r < 4; r++) {
            float xv = Xs2[(r0 + r) * K + k];
            acc0[r] = fmaf(xv, w0, acc0[r]);
            acc1[r] = fmaf(xv, w1, acc1[r]);
        }
    }

    float b0 = B[lane];
    float b1 = (lane + 32 < NOUT) ? B[lane + 32] : 0.f;
    #pragma unroll
    for (int r = 0; r < 4; r++) {
        int gr = row0 + r0 + r;
        if (gr >= n) continue;
        out[(size_t)gr * NOUT + lane] = acc0[r] + b0;
        if (lane + 32 < NOUT) out[(size_t)gr * NOUT + lane + 32] = acc1[r] + b1;
    }
}

// ---------------------------------------------------------------------------
extern "C" void kernel_launch(void* const* d_in, const int* in_sizes, int n_in,
                              void* d_out, int out_size) {
    const float* x    = (const float*)d_in[0];
    const int*   ei   = (const int*)d_in[1];
    const float* W0   = (const float*)d_in[2];
    const float* b0   = (const float*)d_in[3];
    const float* W1   = (const float*)d_in[4];
    const float* b1   = (const float*)d_in[5];
    const float* W2   = (const float*)d_in[6];
    const float* b2   = (const float*)d_in[7];
    const float* Wout = (const float*)d_in[8];
    const float* bout = (const float*)d_in[9];
    float* out = (float*)d_out;

    const int N = in_sizes[0] / F_IN;
    const int E = in_sizes[1] / 2;
    const int* src = ei;
    const int* dst = ei + E;

    __half *uA, *uB, *dish;
    float *dis;
    int *deg, *rowptr, *cursor, *colidx, *bsum;
    cudaGetSymbolAddress((void**)&uA,     g_uA);
    cudaGetSymbolAddress((void**)&uB,     g_uB);
    cudaGetSymbolAddress((void**)&deg,    g_deg);
    cudaGetSymbolAddress((void**)&dis,    g_dis);
    cudaGetSymbolAddress((void**)&dish,   g_dish);
    cudaGetSymbolAddress((void**)&rowptr, g_rowptr);
    cudaGetSymbolAddress((void**)&cursor, g_cursor);
    cudaGetSymbolAddress((void**)&colidx, g_colidx);
    cudaGetSymbolAddress((void**)&bsum,   g_bsum);

    const int TPB = 256;
    int gemmBlocks64 = (N + 63) / 64;               // 1563
    int scatB = (E + TPB - 1) / TPB;                // 6250
    dim3 mega_grid(gemmBlocks64 + scatB);
    dim3 layer_grid(gemmBlocks64);
    dim3 head_grid((N + 31) / 32);
    int nscan = (N + 1023) / 1024;

    // CSR prerequisite chain
    cudaMemsetAsync(deg, 0, N * sizeof(int), 0);
    count_deg_kernel<<<(E + TPB - 1) / TPB, TPB>>>(dst, E, deg);
    scan1_kernel<<<nscan, 256>>>(deg, rowptr, dis, dish, bsum, N);
    scan3_kernel<<<(N + TPB - 1) / TPB, TPB>>>(bsum, rowptr, cursor, N, nscan);

    // Layer-0 GEMM overlapped with CSR edge scatter
    gemm0_scatter_kernel<<<mega_grid, TPB>>>(x, W0, b0, uA, N,
                                             src, dst, cursor, colidx, E, gemmBlocks64);

    // Fused layers
    fused64_kernel<true><<<layer_grid, TPB>>>(rowptr, deg, colidx, dis, dish, uA, W1, b1, uB, N);
    fused64_kernel<false><<<layer_grid, TPB>>>(rowptr, deg, colidx, dis, dish, uB, W2, b2, uA, N);
    fused_head_kernel<<<head_grid, TPB>>>(rowptr, deg, colidx, dis, uA, Wout, bout, out, N);
}